// round 15
// baseline (speedup 1.0000x reference)
#include <cuda_runtime.h>
#include <cuda_fp16.h>
#include <math.h>
#include <stdint.h>

// Problem dims (fixed by the dataset)
#define Bq 4
#define Tq 2048
#define Dq 1024
#define Hq 2048
#define Eq 8
#define Kq 2
#define Nq (Bq*Tq)          // 8192 tokens
#define NROWS (Nq*Kq)       // 16384 (token, expert) pairs
#define MTILES 64           // worst case: one expert gets all 8192 tokens

// GEMM tiling (fp16 path)
#define KT 32                    // k-tile in halfs
#define A_ROW_B 80               // A smem row stride bytes (64B data + 16B pad)
#define B_ROW_B 272              // B smem row stride bytes (256B data + 16B pad)
#define A_STAGE_BYTES (128*A_ROW_B)   // 10240
#define B_STAGE_BYTES (KT*B_ROW_B)    // 8704
#define STAGE_BYTES (A_STAGE_BYTES+B_STAGE_BYTES)  // 18944
#define NSTAGE 3
#define SMEM_BYTES (NSTAGE*STAGE_BYTES)            // 56832

// -------------------- scratch (device globals; no allocation allowed) ------
__device__ int    g_count[Eq];
__device__ int    g_offset[Eq];
__device__ int    g_cursor[Eq];
__device__ float  g_imp_sum[Eq];
__device__ float  g_ent_sum;
__device__ int    g_tk_idx[Nq*Kq];
__device__ float  g_tk_gate[Nq*Kq];
__device__ int    g_tk_row[Nq*Kq];          // token-slot -> compacted row
__device__ int    g_row_token[NROWS];
__device__ float  g_row_gate[NROWS];
__device__ __half g_xh[(size_t)Nq*Dq];      // x in fp16                (16 MB)
__device__ __half g_w1h[(size_t)Eq*Dq*Hq]; // W1 in fp16 [E][D][H]     (32 MB)
__device__ __half g_w2h[(size_t)Eq*Hq*Dq]; // W2 in fp16 [E][H][D]     (32 MB)
__device__ __half g_h[(size_t)NROWS*Hq];   // gelu intermediate fp16   (64 MB)
__device__ float  g_y[(size_t)NROWS*Dq];   // per-slot expert output   (64 MB)

// -------------------- helpers ---------------------------------------------
__device__ __forceinline__ void mma16(float* d,
                                      uint32_t a0, uint32_t a1, uint32_t a2, uint32_t a3,
                                      uint32_t b0, uint32_t b1) {
    asm volatile("mma.sync.aligned.m16n8k16.row.col.f32.f16.f16.f32 "
                 "{%0,%1,%2,%3}, {%4,%5,%6,%7}, {%8,%9}, {%0,%1,%2,%3};"
                 : "+f"(d[0]), "+f"(d[1]), "+f"(d[2]), "+f"(d[3])
                 : "r"(a0), "r"(a1), "r"(a2), "r"(a3), "r"(b0), "r"(b1));
}

#define LDSM_X4(r0, r1, r2, r3, addr) \
    asm volatile("ldmatrix.sync.aligned.m8n8.x4.shared.b16 {%0,%1,%2,%3}, [%4];" \
                 : "=r"(r0), "=r"(r1), "=r"(r2), "=r"(r3) : "r"(addr))

#define LDSM_X4_T(r0, r1, r2, r3, addr) \
    asm volatile("ldmatrix.sync.aligned.m8n8.x4.trans.shared.b16 {%0,%1,%2,%3}, [%4];" \
                 : "=r"(r0), "=r"(r1), "=r"(r2), "=r"(r3) : "r"(addr))

__device__ __forceinline__ void cp16(uint32_t dst, const void* src, int szr) {
    asm volatile("cp.async.cg.shared.global [%0], [%1], 16, %2;"
                 :: "r"(dst), "l"(src), "r"(szr));
}
#define CP_COMMIT() asm volatile("cp.async.commit_group;")
#define CP_WAIT1()  asm volatile("cp.async.wait_group 1;")

__device__ __forceinline__ float gelu_exact(float c) {
    return 0.5f * c * (1.f + erff(c * 0.70710678118654752f));
}

__device__ __forceinline__ uint32_t h2u(__half2 h) {
    return *reinterpret_cast<uint32_t*>(&h);
}

// -------------------- fp32 -> fp16 conversion (8 elems/thread) ------------
__global__ void cvt_k(const float4* __restrict__ in, uint4* __restrict__ out) {
    size_t i = (size_t)blockIdx.x * blockDim.x + threadIdx.x;
    float4 f0 = in[2*i], f1 = in[2*i+1];
    uint4 o;
    o.x = h2u(__floats2half2_rn(f0.x, f0.y));
    o.y = h2u(__floats2half2_rn(f0.z, f0.w));
    o.z = h2u(__floats2half2_rn(f1.x, f1.y));
    o.w = h2u(__floats2half2_rn(f1.z, f1.w));
    out[i] = o;
}

// x conversion + router-state init fused (init writes are order-free)
__global__ void cvt_init_k(const float4* __restrict__ in, uint4* __restrict__ out) {
    size_t i = (size_t)blockIdx.x * blockDim.x + threadIdx.x;
    if (blockIdx.x == 0) {
        int t = threadIdx.x;
        if (t < Eq) { g_count[t] = 0; g_imp_sum[t] = 0.f; }
        if (t == Eq) g_ent_sum = 0.f;
    }
    float4 f0 = in[2*i], f1 = in[2*i+1];
    uint4 o;
    o.x = h2u(__floats2half2_rn(f0.x, f0.y));
    o.y = h2u(__floats2half2_rn(f0.z, f0.w));
    o.z = h2u(__floats2half2_rn(f1.x, f1.y));
    o.w = h2u(__floats2half2_rn(f1.z, f1.w));
    out[i] = o;
}

// -------------------- router: one warp per token --------------------------
__global__ void router_k(const float* __restrict__ x,
                         const float* __restrict__ gw,
                         const float* __restrict__ gb) {
    __shared__ float s_imp[Eq];
    __shared__ int   s_cnt[Eq];
    __shared__ float s_ent;
    int tid = threadIdx.x;
    if (tid < Eq) { s_imp[tid] = 0.f; s_cnt[tid] = 0; }
    if (tid == Eq) s_ent = 0.f;
    __syncthreads();

    int warp = tid >> 5, lane = tid & 31;
    int t = blockIdx.x * 8 + warp;

    float acc[Eq];
    #pragma unroll
    for (int e = 0; e < Eq; e++) acc[e] = 0.f;

    const float* xr = x + (size_t)t * Dq;
    for (int d = lane; d < Dq; d += 32) {
        float xv = xr[d];
        const float* gwr = gw + d * Eq;
        #pragma unroll
        for (int e = 0; e < Eq; e++) acc[e] += xv * gwr[e];
    }
    #pragma unroll
    for (int e = 0; e < Eq; e++) {
        #pragma unroll
        for (int o = 16; o > 0; o >>= 1)
            acc[e] += __shfl_down_sync(0xffffffffu, acc[e], o);
    }

    if (lane == 0) {
        float lg[Eq], p[Eq];
        float mx = -1e30f;
        #pragma unroll
        for (int e = 0; e < Eq; e++) { lg[e] = acc[e] + gb[e]; mx = fmaxf(mx, lg[e]); }
        float se = 0.f;
        #pragma unroll
        for (int e = 0; e < Eq; e++) { p[e] = expf(lg[e] - mx); se += p[e]; }
        float inv = 1.f / se;
        float ent = 0.f;
        #pragma unroll
        for (int e = 0; e < Eq; e++) {
            p[e] *= inv;
            ent -= p[e] * logf(p[e] + 1e-8f);
            atomicAdd(&s_imp[e], p[e]);
        }
        float bv = -1e30f, sv = -1e30f; int bi = 0, si = 0;
        #pragma unroll
        for (int e = 0; e < Eq; e++) {
            float v = lg[e];
            if (v > bv) { sv = bv; si = bi; bv = v; bi = e; }
            else if (v > sv) { sv = v; si = e; }
        }
        float g0 = 1.f / (1.f + expf(sv - bv));
        float g1 = 1.f - g0;
        g_tk_idx[2*t]   = bi;  g_tk_idx[2*t+1]  = si;
        g_tk_gate[2*t]  = g0;  g_tk_gate[2*t+1] = g1;
        atomicAdd(&s_cnt[bi], 1);
        atomicAdd(&s_cnt[si], 1);
        atomicAdd(&s_ent, ent);
    }
    __syncthreads();
    if (tid < Eq) {
        if (s_cnt[tid]) atomicAdd(&g_count[tid], s_cnt[tid]);
        atomicAdd(&g_imp_sum[tid], s_imp[tid]);
    }
    if (tid == Eq) atomicAdd(&g_ent_sum, s_ent);
}

// -------------------- finalize scalars + prefix offsets -------------------
__global__ void finalize_k(float* __restrict__ out_tail) {
    if (threadIdx.x != 0) return;
    int c = 0;
    #pragma unroll
    for (int e = 0; e < Eq; e++) { g_offset[e] = c; g_cursor[e] = c; c += g_count[e]; }
    float invN = 1.f / (float)Nq;
    float bal = 0.f, ue = 0.f;
    #pragma unroll
    for (int e = 0; e < Eq; e++) {
        float imp  = g_imp_sum[e] * invN;
        float load = (float)g_count[e] * invN;
        bal += imp * load;
        ue  -= load * logf(load + 1e-8f);
        out_tail[3 + e]  = load;
        out_tail[11 + e] = imp;
    }
    out_tail[0] = (float)Eq * bal;
    out_tail[1] = g_ent_sum * invN;
    out_tail[2] = ue;
}

// -------------------- scatter: compact per-expert row lists ---------------
__global__ void scatter_k() {
    int t = blockIdx.x * blockDim.x + threadIdx.x;
    if (t >= Nq) return;
    #pragma unroll
    for (int k = 0; k < Kq; k++) {
        int e = g_tk_idx[2*t + k];
        int pos = atomicAdd(&g_cursor[e], 1);
        g_row_token[pos]  = t;
        g_row_gate[pos]   = g_tk_gate[2*t + k];
        g_tk_row[2*t + k] = pos;
    }
}

// ==========================================================================
// fp16 tensor-core grouped GEMMs, 3-stage cp.async ring, ldmatrix-fed.
// Tile 128x128x32(halfs), 256 threads = 8 warps (2m x 4n), warp tile 64x32.
// mma.m16n8k16.f16, fp32 accumulate.
// GEMM2 writes per-slot rows of g_y with plain vectorized stores (each
// compacted row is owned by exactly one block) -- no atomics; the fused
// layernorm sums x + y[slot0] + y[slot1].
// ==========================================================================

// -------------------- GEMM1: h = gelu(Xg @ W1[e] + b1[e]) -----------------
__global__ __launch_bounds__(256, 2) void gemm1_k(const float* __restrict__ b1) {
    int e  = blockIdx.x >> 6;
    int mt = blockIdx.x & 63;
    int rows = g_count[e];
    int m0 = mt * 128;
    if (m0 >= rows) return;
    int base = g_offset[e];
    int n0 = blockIdx.y * 128;

    extern __shared__ __align__(16) char smraw[];
    uint32_t sm0 = (uint32_t)__cvta_generic_to_shared(smraw);
    int tid = threadIdx.x;

    // ---- A loader: 2 threads per row, 2x16B chunks each (64B/row) ----
    int arow = tid >> 1;
    bool av  = (m0 + arow) < rows;
    int atok = av ? g_row_token[base + m0 + arow] : 0;
    const __half* agp = g_xh + (size_t)atok * Dq + (tid & 1) * 16;
    int asz = av ? 16 : 0;
    uint32_t a_sm = sm0 + arow * A_ROW_B + (tid & 1) * 32;

    // ---- B loader: 8 threads per k-row, 2x16B chunks each (256B/row) ----
    int bkr = tid >> 3;
    int bnb = (tid & 7) * 16;
    const __half* bgp = g_w1h + (size_t)e * Dq * Hq + (size_t)bkr * Hq + n0 + bnb;
    uint32_t b_sm = sm0 + A_STAGE_BYTES + bkr * B_ROW_B + bnb * 2;

    // ---- compute indexing ----
    int warp = tid >> 5, lane = tid & 31;
    int wm = (warp >> 2) * 64, wn = (warp & 3) * 32;
    int qr = lane >> 2, qc = lane & 3;
    uint32_t a_lm_off = (uint32_t)((wm + (lane & 15)) * A_ROW_B + (lane >> 4) * 16);
    uint32_t b_lm_off = (uint32_t)(A_STAGE_BYTES + (lane & 15) * B_ROW_B
                                   + (wn + (lane >> 4) * 8) * 2);

    float acc[4][4][4];
    #pragma unroll
    for (int mi = 0; mi < 4; mi++)
        #pragma unroll
        for (int ni = 0; ni < 4; ni++)
            #pragma unroll
            for (int j = 0; j < 4; j++) acc[mi][ni][j] = 0.f;

    #define PF1(kt_, s_) do { \
        uint32_t ao = a_sm + (s_) * STAGE_BYTES; \
        uint32_t bo = b_sm + (s_) * STAGE_BYTES; \
        const __half* ag = agp + (kt_) * KT; \
        const __half* bg = bgp + (size_t)(kt_) * KT * Hq; \
        cp16(ao,      ag,     asz); cp16(ao + 16, ag + 8, asz); \
        cp16(bo,      bg,     16);  cp16(bo + 16, bg + 8, 16); \
    } while (0)

    PF1(0, 0); CP_COMMIT();
    PF1(1, 1); CP_COMMIT();

    const int NKT = Dq / KT;   // 32
    for (int kt = 0; kt < NKT; kt++) {
        int s = kt % NSTAGE;
        CP_WAIT1();
        __syncthreads();
        if (kt + 2 < NKT) PF1(kt + 2, (kt + 2) % NSTAGE);
        CP_COMMIT();
        uint32_t sbase = sm0 + s * STAGE_BYTES;
        uint32_t a_lm = sbase + a_lm_off;
        uint32_t b_lm = sbase + b_lm_off;
        #pragma unroll
        for (int ks8 = 0; ks8 < 2; ks8++) {   // two k16 steps per k-tile
            uint32_t af[4][4], bf[4][2];
            #pragma unroll
            for (int mi = 0; mi < 4; mi++)
                LDSM_X4(af[mi][0], af[mi][1], af[mi][2], af[mi][3],
                        a_lm + mi * (16 * A_ROW_B) + ks8 * 32);
            #pragma unroll
            for (int n2 = 0; n2 < 2; n2++)
                LDSM_X4_T(bf[2*n2][0], bf[2*n2][1], bf[2*n2+1][0], bf[2*n2+1][1],
                          b_lm + n2 * 32 + ks8 * (16 * B_ROW_B));
            #pragma unroll
            for (int mi = 0; mi < 4; mi++)
                #pragma unroll
                for (int ni = 0; ni < 4; ni++)
                    mma16(acc[mi][ni], af[mi][0], af[mi][1], af[mi][2], af[mi][3],
                          bf[ni][0], bf[ni][1]);
        }
    }

    // epilogue: bias + exact gelu -> g_h (fp16)
    #pragma unroll
    for (int mi = 0; mi < 4; mi++) {
        #pragma unroll
        for (int h = 0; h < 2; h++) {
            int r = wm + mi * 16 + qr + h * 8;
            if (m0 + r < rows) {
                size_t gr = (size_t)(base + m0 + r);
                __half* hrow = g_h + gr * Hq;
                #pragma unroll
                for (int ni = 0; ni < 4; ni++) {
                    int c = n0 + wn + ni * 8 + qc * 2;
                    float u = acc[mi][ni][h*2+0] + b1[e * Hq + c];
                    float v = acc[mi][ni][h*2+1] + b1[e * Hq + c + 1];
                    *reinterpret_cast<__half2*>(hrow + c) =
                        __floats2half2_rn(gelu_exact(u), gelu_exact(v));
                }
            }
        }
    }
}

// -------------------- GEMM2: y[row] = gate * (H @ W2[e] + b2[e]) ----------
__global__ __launch_bounds__(256, 2) void gemm2_k(const float* __restrict__ b2) {
    int e  = blockIdx.x >> 6;
    int mt = blockIdx.x & 63;
    int rows = g_count[e];
    int m0 = mt * 128;
    if (m0 >= rows) return;
    int base = g_offset[e];
    int n0 = blockIdx.y * 128;

    extern __shared__ __align__(16) char smraw[];
    uint32_t sm0 = (uint32_t)__cvta_generic_to_shared(smraw);
    int tid = threadIdx.x;

    int arow = tid >> 1;
    bool av  = (m0 + arow) < rows;
    const __half* agp = g_h + (size_t)(base + m0 + (av ? arow : 0)) * Hq + (tid & 1) * 16;
    int asz = av ? 16 : 0;
    uint32_t a_sm = sm0 + arow * A_ROW_B + (tid & 1) * 32;

    int bkr = tid >> 3;
    int bnb = (tid & 7) * 16;
    const __half* bgp = g_w2h + (size_t)e * Hq * Dq + (size_t)bkr * Dq + n0 + bnb;
    uint32_t b_sm = sm0 + A_STAGE_BYTES + bkr * B_ROW_B + bnb * 2;

    int warp = tid >> 5, lane = tid & 31;
    int wm = (warp >> 2) * 64, wn = (warp & 3) * 32;
    int qr = lane >> 2, qc = lane & 3;
    uint32_t a_lm_off = (uint32_t)((wm + (lane & 15)) * A_ROW_B + (lane >> 4) * 16);
    uint32_t b_lm_off = (uint32_t)(A_STAGE_BYTES + (lane & 15) * B_ROW_B
                                   + (wn + (lane >> 4) * 8) * 2);

    float acc[4][4][4];
    #pragma unroll
    for (int mi = 0; mi < 4; mi++)
        #pragma unroll
        for (int ni = 0; ni < 4; ni++)
            #pragma unroll
            for (int j = 0; j < 4; j++) acc[mi][ni][j] = 0.f;

    #define PF2(kt_, s_) do { \
        uint32_t ao = a_sm + (s_) * STAGE_BYTES; \
        uint32_t bo = b_sm + (s_) * STAGE_BYTES; \
        const __half* ag = agp + (kt_) * KT; \
        const __half* bg = bgp + (size_t)(kt_) * KT * Dq; \
        cp16(ao,      ag,     asz); cp16(ao + 16, ag + 8, asz); \
        cp16(bo,      bg,     16);  cp16(bo + 16, bg + 8, 16); \
    } while (0)

    PF2(0, 0); CP_COMMIT();
    PF2(1, 1); CP_COMMIT();

    const int NKT = Hq / KT;   // 64
    for (int kt = 0; kt < NKT; kt++) {
        int s = kt % NSTAGE;
        CP_WAIT1();
        __syncthreads();
        if (kt + 2 < NKT) PF2(kt + 2, (kt + 2) % NSTAGE);
        CP_COMMIT();
        uint32_t sbase = sm0 + s * STAGE_BYTES;
        uint32_t a_lm = sbase + a_lm_off;
        uint32_t b_lm = sbase + b_lm_off;
        #pragma unroll
        for (int ks8 = 0; ks8 < 2; ks8++) {
            uint32_t af[4][4], bf[4][2];
            #pragma unroll
            for (int mi = 0; mi < 4; mi++)
                LDSM_X4(af[mi][0], af[mi][1], af[mi][2], af[mi][3],
                        a_lm + mi * (16 * A_ROW_B) + ks8 * 32);
            #pragma unroll
            for (int n2 = 0; n2 < 2; n2++)
                LDSM_X4_T(bf[2*n2][0], bf[2*n2][1], bf[2*n2+1][0], bf[2*n2+1][1],
                          b_lm + n2 * 32 + ks8 * (16 * B_ROW_B));
            #pragma unroll
            for (int mi = 0; mi < 4; mi++)
                #pragma unroll
                for (int ni = 0; ni < 4; ni++)
                    mma16(acc[mi][ni], af[mi][0], af[mi][1], af[mi][2], af[mi][3],
                          bf[ni][0], bf[ni][1]);
        }
    }

    // epilogue: y[row] = gate * (acc + b2)  -- plain vectorized stores
    #pragma unroll
    for (int mi = 0; mi < 4; mi++) {
        #pragma unroll
        for (int h = 0; h < 2; h++) {
            int r = wm + mi * 16 + qr + h * 8;
            if (m0 + r < rows) {
                int gr = base + m0 + r;
                float gt = g_row_gate[gr];
                float* yr = g_y + (size_t)gr * Dq;
                #pragma unroll
                for (int ni = 0; ni < 4; ni++) {
                    int c = n0 + wn + ni * 8 + qc * 2;
                    float2 o;
                    o.x = gt * (acc[mi][ni][h*2+0] + b2[e * Dq + c]);
                    o.y = gt * (acc[mi][ni][h*2+1] + b2[e * Dq + c + 1]);
                    *reinterpret_cast<float2*>(yr + c) = o;
                }
            }
        }
    }
}

// ---- fused residual + layernorm: z = x + y[slot0] + y[slot1], then LN ----
__global__ void ln_k(const float* __restrict__ x,
                     const float* __restrict__ gamma,
                     const float* __restrict__ beta,
                     float* __restrict__ out) {
    int t = blockIdx.x;
    int tid = threadIdx.x;
    int r0 = g_tk_row[2*t], r1 = g_tk_row[2*t+1];
    const float4* x4 = reinterpret_cast<const float4*>(x + (size_t)t * Dq);
    const float4* y0 = reinterpret_cast<const float4*>(g_y + (size_t)r0 * Dq);
    const float4* y1 = reinterpret_cast<const float4*>(g_y + (size_t)r1 * Dq);
    float4 a = x4[tid], b = y0[tid], c = y1[tid];
    float4 v;
    v.x = a.x + b.x + c.x;
    v.y = a.y + b.y + c.y;
    v.z = a.z + b.z + c.z;
    v.w = a.w + b.w + c.w;
    float s  = v.x + v.y + v.z + v.w;
    float ss = v.x*v.x + v.y*v.y + v.z*v.z + v.w*v.w;

    #pragma unroll
    for (int o = 16; o > 0; o >>= 1) {
        s  += __shfl_down_sync(0xffffffffu, s, o);
        ss += __shfl_down_sync(0xffffffffu, ss, o);
    }
    __shared__ float rs[8], rss[8];
    int warp = tid >> 5, lane = tid & 31;
    if (lane == 0) { rs[warp] = s; rss[warp] = ss; }
    __syncthreads();
    if (warp == 0) {
        float a2 = (lane < 8) ? rs[lane] : 0.f;
        float b2 = (lane < 8) ? rss[lane] : 0.f;
        #pragma unroll
        for (int o = 4; o > 0; o >>= 1) {
            a2 += __shfl_down_sync(0xffffffffu, a2, o);
            b2 += __shfl_down_sync(0xffffffffu, b2, o);
        }
        if (lane == 0) { rs[0] = a2; rss[0] = b2; }
    }
    __syncthreads();
    float mu  = rs[0] * (1.f / Dq);
    float var = rss[0] * (1.f / Dq) - mu * mu;
    float rstd = rsqrtf(var + 1e-5f);

    float4 g = reinterpret_cast<const float4*>(gamma)[tid];
    float4 bta = reinterpret_cast<const float4*>(beta)[tid];
    float4 o4;
    o4.x = (v.x - mu) * rstd * g.x + bta.x;
    o4.y = (v.y - mu) * rstd * g.y + bta.y;
    o4.z = (v.z - mu) * rstd * g.z + bta.z;
    o4.w = (v.w - mu) * rstd * g.w + bta.w;
    reinterpret_cast<float4*>(out + (size_t)t * Dq)[tid] = o4;
}

// -------------------- launch ----------------------------------------------
extern "C" void kernel_launch(void* const* d_in, const int* in_sizes, int n_in,
                              void* d_out, int out_size) {
    const float* x     = (const float*)d_in[0];
    const float* gw    = (const float*)d_in[1];
    const float* gb    = (const float*)d_in[2];
    const float* W1    = (const float*)d_in[3];
    const float* b1    = (const float*)d_in[4];
    const float* W2    = (const float*)d_in[5];
    const float* b2    = (const float*)d_in[6];
    const float* gamma = (const float*)d_in[7];
    const float* beta  = (const float*)d_in[8];
    float* out = (float*)d_out;

    static bool attr_set = false;
    if (!attr_set) {
        cudaFuncSetAttribute(gemm1_k, cudaFuncAttributeMaxDynamicSharedMemorySize, SMEM_BYTES);
        cudaFuncSetAttribute(gemm2_k, cudaFuncAttributeMaxDynamicSharedMemorySize, SMEM_BYTES);
        attr_set = true;
    }

    __half* xh;  cudaGetSymbolAddress((void**)&xh,  g_xh);
    __half* w1h; cudaGetSymbolAddress((void**)&w1h, g_w1h);
    __half* w2h; cudaGetSymbolAddress((void**)&w2h, g_w2h);

    // fp32 -> fp16 conversions (x conversion also inits router state)
    cvt_init_k<<<(Nq*Dq/8)/256, 256>>>((const float4*)x, (uint4*)xh);
    cvt_k<<<((size_t)Eq*Dq*Hq/8)/256, 256>>>((const float4*)W1, (uint4*)w1h);
    cvt_k<<<((size_t)Eq*Hq*Dq/8)/256, 256>>>((const float4*)W2, (uint4*)w2h);

    router_k<<<Nq / 8, 256>>>(x, gw, gb);
    finalize_k<<<1, 32>>>(out + (size_t)Nq * Dq);
    scatter_k<<<Nq / 256, 256>>>();
    gemm1_k<<<dim3(Eq * MTILES, Hq / 128), 256, SMEM_BYTES>>>(b1);
    gemm2_k<<<dim3(Eq * MTILES, Dq / 128), 256, SMEM_BYTES>>>(b2);
    ln_k<<<Nq, 256>>>(x, gamma, beta, out);
    (void)in_sizes; (void)n_in; (void)out_size;
}